// round 7
// baseline (speedup 1.0000x reference)
#include <cuda_runtime.h>
#include <cuda_bf16.h>
#include <mma.h>

using namespace nvcuda;

#define NB 8
#define NSEQ 1024
#define NH 8
#define HD 64
#define CDIM 512

// Same scratch as the passing round-2 kernel (all fp32, 320 MB)
__device__ float g_q[NB*NH*NSEQ*HD];
__device__ float g_k[NB*NH*NSEQ*HD];
__device__ float g_v[NB*NH*NSEQ*HD];
__device__ float g_s[(size_t)NB*NH*NSEQ*NSEQ];   // 256 MB
__device__ float g_oh[NB*NSEQ*CDIM];

#define EPI_QKV  0
#define EPI_DOTS 1
#define EPI_PV   2
#define EPI_OUT  3

using FragA = wmma::fragment<wmma::matrix_a, 16, 16, 8, wmma::precision::tf32, wmma::col_major>;
using FragB = wmma::fragment<wmma::matrix_b, 16, 16, 8, wmma::precision::tf32, wmma::row_major>;
using FragC = wmma::fragment<wmma::accumulator, 16, 16, 8, float>;

template<class Frag>
__device__ __forceinline__ void split_frag(const Frag& f, Frag& h, Frag& l) {
    #pragma unroll
    for (int i = 0; i < f.num_elements; i++) {
        const float v  = f.x[i];
        const float hv = wmma::__float_to_tf32(v);
        h.x[i] = hv;
        l.x[i] = wmma::__float_to_tf32(v - hv);
    }
}

// ---------------------------------------------------------------------------
// tf32-split wmma GEMM. Tile 128x64, BK=8 (= one wmma k-step).
// Loaders / epilogue index math cloned from the round-2 kernel that PASSED.
//   EPI 0: QKV scatter  1: dots*scale->g_s  2: PV->g_oh  3: +bias->out
// ---------------------------------------------------------------------------
template<int EPI, int KD, int LDA_, int LDB_, bool TRANSB>
__global__ __launch_bounds__(256)
void tgemm(const float* __restrict__ Ain, const float* __restrict__ Bin,
           const float* __restrict__ bias, float* __restrict__ Cout)
{
    constexpr int BM = 128, BN = 64, BK = 8, KT = KD / BK;
    __shared__ float As[BK][BM];
    __shared__ float Bs[BK][BN];
    __shared__ float stage[BM*BN];   // 32 KB epilogue staging

    const int t    = threadIdx.x;
    const int wid  = t >> 5;
    const int wm   = wid & 3, wn = wid >> 2;   // warp tile origin (wm*32, wn*32)
    const int m0   = blockIdx.y * BM;
    const int n0   = blockIdx.x * BN;
    const int z    = blockIdx.z;

    const float* Ap;
    const float* Bp;
    if      constexpr (EPI == EPI_QKV)  { Ap = Ain;                     Bp = Bin; }
    else if constexpr (EPI == EPI_DOTS) { Ap = g_q + (size_t)z*NSEQ*HD; Bp = g_k + (size_t)z*NSEQ*HD; }
    else if constexpr (EPI == EPI_PV)   { Ap = g_s + ((size_t)z << 20); Bp = g_v + (size_t)z*NSEQ*HD; }
    else                                { Ap = g_oh;                    Bp = Bin; }

    // A loader: 128 rows x 8 k, one float4/thread (round-2 proven)
    const int arow  = t >> 1;
    const int acolk = (t & 1) * 4;
    // B loader: 64x8 = 128 float4s -> threads t<128
    const bool bact = (t < 128);
    int brow, bcol;
    if constexpr (TRANSB) { brow = t >> 1; bcol = (t & 1) * 4; }   // brow = local n, bcol = k
    else                  { brow = t >> 4; bcol = (t & 15) * 4; }  // brow = k, bcol = local n

    FragC acc[2][2];
    #pragma unroll
    for (int i = 0; i < 2; i++)
        #pragma unroll
        for (int j = 0; j < 2; j++) wmma::fill_fragment(acc[i][j], 0.f);

    float4 rA = make_float4(0,0,0,0), rB = make_float4(0,0,0,0);

    // prologue: tile 0
    rA = *reinterpret_cast<const float4*>(Ap + (size_t)(m0 + arow) * LDA_ + acolk);
    if (bact) {
        if constexpr (TRANSB) rB = *reinterpret_cast<const float4*>(Bp + (size_t)(n0 + brow) * LDB_ + bcol);
        else                  rB = *reinterpret_cast<const float4*>(Bp + (size_t)brow * LDB_ + n0 + bcol);
    }
    As[acolk+0][arow]=rA.x; As[acolk+1][arow]=rA.y; As[acolk+2][arow]=rA.z; As[acolk+3][arow]=rA.w;
    if (bact) {
        if constexpr (TRANSB) {
            Bs[bcol+0][brow]=rB.x; Bs[bcol+1][brow]=rB.y; Bs[bcol+2][brow]=rB.z; Bs[bcol+3][brow]=rB.w;
        } else {
            *reinterpret_cast<float4*>(&Bs[brow][bcol]) = rB;
        }
    }
    __syncthreads();

    for (int kt = 0; kt < KT; kt++) {
        if (kt + 1 < KT) {
            const int k1 = (kt + 1) * BK;
            rA = *reinterpret_cast<const float4*>(Ap + (size_t)(m0 + arow) * LDA_ + k1 + acolk);
            if (bact) {
                if constexpr (TRANSB) rB = *reinterpret_cast<const float4*>(Bp + (size_t)(n0 + brow) * LDB_ + k1 + bcol);
                else                  rB = *reinterpret_cast<const float4*>(Bp + (size_t)(k1 + brow) * LDB_ + n0 + bcol);
            }
        }

        // compute: one wmma k-step over As[8][128] / Bs[8][64]
        {
            FragA fah[2], fal[2];
            FragB fbh[2], fbl[2];
            #pragma unroll
            for (int im = 0; im < 2; im++) {
                FragA fa;
                wmma::load_matrix_sync(fa, &As[0][wm*32 + im*16], BM);   // col-major, ld=128
                split_frag(fa, fah[im], fal[im]);
            }
            #pragma unroll
            for (int in_ = 0; in_ < 2; in_++) {
                FragB fb;
                wmma::load_matrix_sync(fb, &Bs[0][wn*32 + in_*16], BN);  // row-major, ld=64
                split_frag(fb, fbh[in_], fbl[in_]);
            }
            #pragma unroll
            for (int im = 0; im < 2; im++)
                #pragma unroll
                for (int in_ = 0; in_ < 2; in_++) {
                    wmma::mma_sync(acc[im][in_], fah[im], fbh[in_], acc[im][in_]);
                    wmma::mma_sync(acc[im][in_], fah[im], fbl[in_], acc[im][in_]);
                    wmma::mma_sync(acc[im][in_], fal[im], fbh[in_], acc[im][in_]);
                }
        }
        __syncthreads();

        if (kt + 1 < KT) {
            As[acolk+0][arow]=rA.x; As[acolk+1][arow]=rA.y; As[acolk+2][arow]=rA.z; As[acolk+3][arow]=rA.w;
            if (bact) {
                if constexpr (TRANSB) {
                    Bs[bcol+0][brow]=rB.x; Bs[bcol+1][brow]=rB.y; Bs[bcol+2][brow]=rB.z; Bs[bcol+3][brow]=rB.w;
                } else {
                    *reinterpret_cast<float4*>(&Bs[brow][bcol]) = rB;
                }
            }
            __syncthreads();
        }
    }

    // drain accumulators -> smem stage -> scatter (round-2 index math)
    #pragma unroll
    for (int im = 0; im < 2; im++)
        #pragma unroll
        for (int in_ = 0; in_ < 2; in_++)
            wmma::store_matrix_sync(&stage[(wm*32 + im*16)*BN + wn*32 + in_*16],
                                    acc[im][in_], BN, wmma::mem_row_major);
    __syncthreads();

    for (int idx = t; idx < BM*BN; idx += 256) {
        const int lr = idx >> 6, lc = idx & 63;
        const float v = stage[idx];
        const int r = m0 + lr, c = n0 + lc;
        if constexpr (EPI == EPI_QKV) {
            const int part = c >> 9, rem = c & 511;
            const int h = rem >> 6, d = rem & 63;
            const int b = r >> 10, n = r & 1023;
            float* dst = (part == 0) ? g_q : (part == 1) ? g_k : g_v;
            dst[(((size_t)(b*NH + h))*NSEQ + n)*HD + d] = v;
        } else if constexpr (EPI == EPI_DOTS) {
            g_s[((size_t)z << 20) + (size_t)r*NSEQ + c] = v * 0.125f;
        } else if constexpr (EPI == EPI_PV) {
            const int b = z >> 3, h = z & 7;
            g_oh[((size_t)(b*NSEQ + r))*CDIM + h*HD + c] = v;
        } else {
            Cout[(size_t)r*CDIM + c] = v + bias[c];
        }
    }
}

// ---------------------------------------------------------------------------
// softmax + remix + LN (identical to round-2 passing version; in-place on g_s)
// ---------------------------------------------------------------------------
__global__ __launch_bounds__(256)
void softmax_remix_ln(const float* __restrict__ W,
                      const float* __restrict__ gamma,
                      const float* __restrict__ beta)
{
    __shared__ float s[NH][NSEQ];
    __shared__ float w_s[64], g_s_[8], b_s_[8];

    const int t = threadIdx.x;
    const int bi = blockIdx.x;
    const int b = bi >> 10, i = bi & 1023;

    if (t < 64) w_s[t] = W[t];
    if (t >= 64 && t < 72) { g_s_[t-64] = gamma[t-64]; b_s_[t-64] = beta[t-64]; }

    const int wid = t >> 5, lid = t & 31;
    {
        const float* row = g_s + (((size_t)(b*NH + wid))*NSEQ + i)*NSEQ;
        float v[32], m = -1e30f;
        #pragma unroll
        for (int u = 0; u < 32; u++) { v[u] = row[lid + 32*u]; m = fmaxf(m, v[u]); }
        #pragma unroll
        for (int o = 16; o > 0; o >>= 1) m = fmaxf(m, __shfl_xor_sync(0xffffffffu, m, o));
        float sum = 0.f;
        #pragma unroll
        for (int u = 0; u < 32; u++) { v[u] = __expf(v[u] - m); sum += v[u]; }
        #pragma unroll
        for (int o = 16; o > 0; o >>= 1) sum += __shfl_xor_sync(0xffffffffu, sum, o);
        const float inv = 1.f / sum;
        #pragma unroll
        for (int u = 0; u < 32; u++) s[wid][lid + 32*u] = v[u] * inv;
    }
    __syncthreads();

    #pragma unroll
    for (int u = 0; u < 4; u++) {
        const int j = t + 256*u;
        float a[8], mres[8];
        #pragma unroll
        for (int h = 0; h < 8; h++) a[h] = s[h][j];
        float mean = 0.f;
        #pragma unroll
        for (int g = 0; g < 8; g++) {
            float acc = 0.f;
            #pragma unroll
            for (int h = 0; h < 8; h++) acc += a[h] * w_s[h*8 + g];
            mres[g] = acc; mean += acc;
        }
        mean *= 0.125f;
        float var = 0.f;
        #pragma unroll
        for (int g = 0; g < 8; g++) { float d = mres[g] - mean; var += d*d; }
        var *= 0.125f;
        const float rstd = rsqrtf(var + 1e-5f);
        #pragma unroll
        for (int g = 0; g < 8; g++) {
            const float o = (mres[g] - mean) * rstd * g_s_[g] + b_s_[g];
            g_s[(((size_t)(b*NH + g))*NSEQ + i)*NSEQ + j] = o;
        }
    }
}

// ---------------------------------------------------------------------------
extern "C" void kernel_launch(void* const* d_in, const int* in_sizes, int n_in,
                              void* d_out, int out_size)
{
    const float* x      = (const float*)d_in[0];
    const float* w_qkv  = (const float*)d_in[1];
    const float* reattn = (const float*)d_in[2];
    const float* gamma  = (const float*)d_in[3];
    const float* beta   = (const float*)d_in[4];
    const float* w_out  = (const float*)d_in[5];
    const float* b_out  = (const float*)d_in[6];
    float* out = (float*)d_out;

    // 1) qkv = x @ w_qkv -> scatter g_q/g_k/g_v
    tgemm<EPI_QKV, 512, 512, 1536, false>
        <<<dim3(24, 64, 1), 256>>>(x, w_qkv, nullptr, nullptr);
    // 2) dots = q @ k^T * scale (B = k[j][d], transposed in loader)
    tgemm<EPI_DOTS, 64, 64, 64, true>
        <<<dim3(16, 8, 64), 256>>>(nullptr, nullptr, nullptr, nullptr);
    // 3) softmax + remix + LN (in place on g_s)
    softmax_remix_ln<<<NB*NSEQ, 256>>>(reattn, gamma, beta);
    // 4) out_h = attn @ v
    tgemm<EPI_PV, 1024, 1024, 64, false>
        <<<dim3(1, 8, 64), 256>>>(nullptr, nullptr, nullptr, nullptr);
    // 5) out = g_oh @ w_out + b_out
    tgemm<EPI_OUT, 512, 512, 512, false>
        <<<dim3(8, 64, 1), 256>>>(nullptr, w_out, b_out, out);
}

// round 8
// speedup vs baseline: 1.1044x; 1.1044x over previous
#include <cuda_runtime.h>
#include <cuda_bf16.h>
#include <mma.h>

using namespace nvcuda;

#define NB 8
#define NSEQ 1024
#define NH 8
#define HD 64
#define CDIM 512

__device__ float g_q[NB*NH*NSEQ*HD];
__device__ float g_k[NB*NH*NSEQ*HD];
__device__ float g_v[NB*NH*NSEQ*HD];
__device__ float g_s[(size_t)NB*NH*NSEQ*NSEQ];   // 256 MB
__device__ float g_oh[NB*NSEQ*CDIM];

#define EPI_QKV  0
#define EPI_DOTS 1
#define EPI_PV   2
#define EPI_OUT  3

using FragAR = wmma::fragment<wmma::matrix_a, 16, 16, 8, wmma::precision::tf32, wmma::row_major>;
using FragBR = wmma::fragment<wmma::matrix_b, 16, 16, 8, wmma::precision::tf32, wmma::row_major>;
using FragBC = wmma::fragment<wmma::matrix_b, 16, 16, 8, wmma::precision::tf32, wmma::col_major>;
using FragC  = wmma::fragment<wmma::accumulator, 16, 16, 8, float>;

template<class Frag>
__device__ __forceinline__ void split_frag(const Frag& f, Frag& h, Frag& l) {
    #pragma unroll
    for (int i = 0; i < f.num_elements; i++) {
        const float v  = f.x[i];
        const float hv = wmma::__float_to_tf32(v);
        h.x[i] = hv;
        l.x[i] = wmma::__float_to_tf32(v - hv);
    }
}

// ---------------------------------------------------------------------------
// tf32-split wmma GEMM. Tile 128x64, BK=32 (4 wmma k-steps), double-buffered,
// one __syncthreads per k-tile, direct global epilogue (no staging).
// smem: As[2][128][36] fp32 (row-major A), then
//       TRANSB ? Bs[2][64][36] (B as col-major)  :  Bs[2][32][68] (row-major)
// ---------------------------------------------------------------------------
template<int EPI, int KD, int LDA_, int LDB_, bool TRANSB>
__global__ __launch_bounds__(256)
void tgemm(const float* __restrict__ Ain, const float* __restrict__ Bin,
           float* __restrict__ Cout)
{
    constexpr int BM = 128, BN = 64, BK = 32, KT = KD / BK;
    constexpr int LDAS = 36;
    constexpr int LDBS = TRANSB ? 36 : 68;
    constexpr int A_STG = BM * LDAS;                       // floats per A stage
    constexpr int B_STG = TRANSB ? (BN * 36) : (BK * 68);  // floats per B stage

    extern __shared__ float sm[];
    float* As = sm;                  // [2][A_STG]
    float* Bs = sm + 2 * A_STG;      // [2][B_STG]

    const int t   = threadIdx.x;
    const int wid = t >> 5;
    const int wm  = wid & 3, wn = wid >> 2;   // warp origin (wm*32, wn*32)
    const int m0  = blockIdx.y * BM;
    const int n0  = blockIdx.x * BN;
    const int z   = blockIdx.z;

    const float* Ap;
    const float* Bp;
    if      constexpr (EPI == EPI_QKV)  { Ap = Ain;                     Bp = Bin; }
    else if constexpr (EPI == EPI_DOTS) { Ap = g_q + (size_t)z*NSEQ*HD; Bp = g_k + (size_t)z*NSEQ*HD; }
    else if constexpr (EPI == EPI_PV)   { Ap = g_s + ((size_t)z << 20); Bp = g_v + (size_t)z*NSEQ*HD; }
    else                                { Ap = g_oh;                    Bp = Bin; }

    // ---- loaders (register prefetch; all coalesced float4) ----
    float4 rA[4], rB[2];

    auto fetchA = [&](int k0) {
        #pragma unroll
        for (int i = 0; i < 4; i++) {
            const int idx = t + i*256;                 // 1024 float4: 128 rows x 8
            const int row = idx >> 3, k4 = (idx & 7) * 4;
            rA[i] = *reinterpret_cast<const float4*>(Ap + (size_t)(m0 + row) * LDA_ + k0 + k4);
        }
    };
    auto fetchB = [&](int k0) {
        #pragma unroll
        for (int i = 0; i < 2; i++) {
            const int idx = t + i*256;                 // 512 float4
            if constexpr (TRANSB) {                    // 64 n-rows x 8 k-float4
                const int row = idx >> 3, k4 = (idx & 7) * 4;
                rB[i] = *reinterpret_cast<const float4*>(Bp + (size_t)(n0 + row) * LDB_ + k0 + k4);
            } else {                                   // 32 k-rows x 16 n-float4
                const int row = idx >> 4, n4 = (idx & 15) * 4;
                rB[i] = *reinterpret_cast<const float4*>(Bp + (size_t)(k0 + row) * LDB_ + n0 + n4);
            }
        }
    };
    auto stage = [&](int st) {
        float* a = As + st * A_STG;
        #pragma unroll
        for (int i = 0; i < 4; i++) {
            const int idx = t + i*256;
            const int row = idx >> 3, k4 = (idx & 7) * 4;
            *reinterpret_cast<float4*>(a + row*LDAS + k4) = rA[i];
        }
        float* b = Bs + st * B_STG;
        #pragma unroll
        for (int i = 0; i < 2; i++) {
            const int idx = t + i*256;
            if constexpr (TRANSB) {
                const int row = idx >> 3, k4 = (idx & 7) * 4;
                *reinterpret_cast<float4*>(b + row*36 + k4) = rB[i];
            } else {
                const int row = idx >> 4, n4 = (idx & 15) * 4;
                *reinterpret_cast<float4*>(b + row*68 + n4) = rB[i];
            }
        }
    };

    FragC acc[2][2];
    #pragma unroll
    for (int i = 0; i < 2; i++)
        #pragma unroll
        for (int j = 0; j < 2; j++) wmma::fill_fragment(acc[i][j], 0.f);

    fetchA(0); fetchB(0);
    stage(0);
    __syncthreads();

    for (int kt = 0; kt < KT; kt++) {
        const int st = kt & 1;
        if (kt + 1 < KT) { fetchA((kt+1)*BK); fetchB((kt+1)*BK); }

        const float* a = As + st * A_STG;
        const float* b = Bs + st * B_STG;
        #pragma unroll
        for (int ks = 0; ks < 4; ks++) {
            FragAR fah[2], fal[2];
            #pragma unroll
            for (int im = 0; im < 2; im++) {
                FragAR fa;
                wmma::load_matrix_sync(fa, a + (wm*32 + im*16)*LDAS + ks*8, LDAS);
                split_frag(fa, fah[im], fal[im]);
            }
            if constexpr (TRANSB) {
                FragBC fbh[2], fbl[2];
                #pragma unroll
                for (int in_ = 0; in_ < 2; in_++) {
                    FragBC fb;
                    wmma::load_matrix_sync(fb, b + (wn*32 + in_*16)*36 + ks*8, 36);
                    split_frag(fb, fbh[in_], fbl[in_]);
                }
                #pragma unroll
                for (int im = 0; im < 2; im++)
                    #pragma unroll
                    for (int in_ = 0; in_ < 2; in_++) {
                        wmma::mma_sync(acc[im][in_], fah[im], fbh[in_], acc[im][in_]);
                        wmma::mma_sync(acc[im][in_], fah[im], fbl[in_], acc[im][in_]);
                        wmma::mma_sync(acc[im][in_], fal[im], fbh[in_], acc[im][in_]);
                    }
            } else {
                FragBR fbh[2], fbl[2];
                #pragma unroll
                for (int in_ = 0; in_ < 2; in_++) {
                    FragBR fb;
                    wmma::load_matrix_sync(fb, b + (ks*8)*68 + wn*32 + in_*16, 68);
                    split_frag(fb, fbh[in_], fbl[in_]);
                }
                #pragma unroll
                for (int im = 0; im < 2; im++)
                    #pragma unroll
                    for (int in_ = 0; in_ < 2; in_++) {
                        wmma::mma_sync(acc[im][in_], fah[im], fbh[in_], acc[im][in_]);
                        wmma::mma_sync(acc[im][in_], fah[im], fbl[in_], acc[im][in_]);
                        wmma::mma_sync(acc[im][in_], fal[im], fbh[in_], acc[im][in_]);
                    }
            }
        }

        if (kt + 1 < KT) stage(st ^ 1);
        __syncthreads();
    }

    // ---- direct-to-global epilogue ----
    float* dst; int ldd;
    if constexpr (EPI == EPI_QKV) {
        // whole 64-wide tile lies in one (part, h); rows in one b
        const int part = n0 >> 9, h = (n0 & 511) >> 6;
        const int b = m0 >> 10, nr = m0 & 1023;
        float* base = (part == 0) ? g_q : (part == 1) ? g_k : g_v;
        dst = base + (((size_t)(b*NH + h))*NSEQ + nr)*HD;
        ldd = HD;
    } else if constexpr (EPI == EPI_DOTS) {
        dst = g_s + ((size_t)z << 20) + (size_t)m0*NSEQ + n0;
        ldd = NSEQ;
        #pragma unroll
        for (int im = 0; im < 2; im++)
            #pragma unroll
            for (int in_ = 0; in_ < 2; in_++)
                #pragma unroll
                for (int e = 0; e < acc[0][0].num_elements; e++)
                    acc[im][in_].x[e] *= 0.125f;
    } else if constexpr (EPI == EPI_PV) {
        const int b = z >> 3, h = z & 7;
        dst = g_oh + ((size_t)(b*NSEQ + m0))*CDIM + h*HD + n0;
        ldd = CDIM;
    } else {
        dst = Cout + (size_t)m0*CDIM + n0;
        ldd = CDIM;
    }
    #pragma unroll
    for (int im = 0; im < 2; im++)
        #pragma unroll
        for (int in_ = 0; in_ < 2; in_++)
            wmma::store_matrix_sync(dst + (size_t)(wm*32 + im*16)*ldd + wn*32 + in_*16,
                                    acc[im][in_], ldd, wmma::mem_row_major);
}

// out[m][c] += bias[c]
__global__ void bias_add_k(float* __restrict__ out, const float* __restrict__ bias)
{
    const int i = blockIdx.x * blockDim.x + threadIdx.x;
    out[i] += bias[i & (CDIM-1)];
}

// ---------------------------------------------------------------------------
// softmax + remix + LN (unchanged; in-place on g_s)
// ---------------------------------------------------------------------------
__global__ __launch_bounds__(256)
void softmax_remix_ln(const float* __restrict__ W,
                      const float* __restrict__ gamma,
                      const float* __restrict__ beta)
{
    __shared__ float s[NH][NSEQ];
    __shared__ float w_s[64], g_s_[8], b_s_[8];

    const int t = threadIdx.x;
    const int bi = blockIdx.x;
    const int b = bi >> 10, i = bi & 1023;

    if (t < 64) w_s[t] = W[t];
    if (t >= 64 && t < 72) { g_s_[t-64] = gamma[t-64]; b_s_[t-64] = beta[t-64]; }

    const int wid = t >> 5, lid = t & 31;
    {
        const float* row = g_s + (((size_t)(b*NH + wid))*NSEQ + i)*NSEQ;
        float v[32], m = -1e30f;
        #pragma unroll
        for (int u = 0; u < 32; u++) { v[u] = row[lid + 32*u]; m = fmaxf(m, v[u]); }
        #pragma unroll
        for (int o = 16; o > 0; o >>= 1) m = fmaxf(m, __shfl_xor_sync(0xffffffffu, m, o));
        float sum = 0.f;
        #pragma unroll
        for (int u = 0; u < 32; u++) { v[u] = __expf(v[u] - m); sum += v[u]; }
        #pragma unroll
        for (int o = 16; o > 0; o >>= 1) sum += __shfl_xor_sync(0xffffffffu, sum, o);
        const float inv = 1.f / sum;
        #pragma unroll
        for (int u = 0; u < 32; u++) s[wid][lid + 32*u] = v[u] * inv;
    }
    __syncthreads();

    #pragma unroll
    for (int u = 0; u < 4; u++) {
        const int j = t + 256*u;
        float a[8], mres[8];
        #pragma unroll
        for (int h = 0; h < 8; h++) a[h] = s[h][j];
        float mean = 0.f;
        #pragma unroll
        for (int g = 0; g < 8; g++) {
            float acc = 0.f;
            #pragma unroll
            for (int h = 0; h < 8; h++) acc += a[h] * w_s[h*8 + g];
            mres[g] = acc; mean += acc;
        }
        mean *= 0.125f;
        float var = 0.f;
        #pragma unroll
        for (int g = 0; g < 8; g++) { float d = mres[g] - mean; var += d*d; }
        var *= 0.125f;
        const float rstd = rsqrtf(var + 1e-5f);
        #pragma unroll
        for (int g = 0; g < 8; g++) {
            const float o = (mres[g] - mean) * rstd * g_s_[g] + b_s_[g];
            g_s[(((size_t)(b*NH + g))*NSEQ + i)*NSEQ + j] = o;
        }
    }
}

// ---------------------------------------------------------------------------
extern "C" void kernel_launch(void* const* d_in, const int* in_sizes, int n_in,
                              void* d_out, int out_size)
{
    const float* x      = (const float*)d_in[0];
    const float* w_qkv  = (const float*)d_in[1];
    const float* reattn = (const float*)d_in[2];
    const float* gamma  = (const float*)d_in[3];
    const float* beta   = (const float*)d_in[4];
    const float* w_out  = (const float*)d_in[5];
    const float* b_out  = (const float*)d_in[6];
    float* out = (float*)d_out;

    constexpr int SM_A   = 2*128*36*4;             // 36864 B
    constexpr int SM_ROW = SM_A + 2*32*68*4;       // 54272 B (row-major B)
    constexpr int SM_COL = SM_A + 2*64*36*4;       // 55296 B (col-major B / TRANSB)

    cudaFuncSetAttribute(tgemm<EPI_QKV, 512, 512, 1536, false>, cudaFuncAttributeMaxDynamicSharedMemorySize, SM_ROW);
    cudaFuncSetAttribute(tgemm<EPI_DOTS, 64, 64, 64, true>,     cudaFuncAttributeMaxDynamicSharedMemorySize, SM_COL);
    cudaFuncSetAttribute(tgemm<EPI_PV, 1024, 1024, 64, false>,  cudaFuncAttributeMaxDynamicSharedMemorySize, SM_ROW);
    cudaFuncSetAttribute(tgemm<EPI_OUT, 512, 512, 512, false>,  cudaFuncAttributeMaxDynamicSharedMemorySize, SM_ROW);

    // 1) qkv = x @ w_qkv -> scatter g_q/g_k/g_v
    tgemm<EPI_QKV, 512, 512, 1536, false>
        <<<dim3(24, 64, 1), 256, SM_ROW>>>(x, w_qkv, nullptr);
    // 2) dots = q @ k^T * scale
    tgemm<EPI_DOTS, 64, 64, 64, true>
        <<<dim3(16, 8, 64), 256, SM_COL>>>(nullptr, nullptr, nullptr);
    // 3) softmax + remix + LN (in place on g_s)
    softmax_remix_ln<<<NB*NSEQ, 256>>>(reattn, gamma, beta);
    // 4) out_h = attn @ v
    tgemm<EPI_PV, 1024, 1024, 64, false>
        <<<dim3(1, 8, 64), 256, SM_ROW>>>(nullptr, nullptr, nullptr);
    // 5) out = g_oh @ w_out ; then + b_out
    tgemm<EPI_OUT, 512, 512, 512, false>
        <<<dim3(8, 64, 1), 256, SM_ROW>>>(nullptr, w_out, out);
    bias_add_k<<<(8192*512)/256, 256>>>(out, b_out);
}

// round 9
// speedup vs baseline: 1.3642x; 1.2352x over previous
#include <cuda_runtime.h>
#include <cuda_bf16.h>
#include <mma.h>

using namespace nvcuda;

#define NB 8
#define NSEQ 1024
#define NH 8
#define HD 64
#define CDIM 512

__device__ float g_q[NB*NH*NSEQ*HD];
__device__ float g_k[NB*NH*NSEQ*HD];
__device__ float g_v[NB*NH*NSEQ*HD];
__device__ float g_s[(size_t)NB*NH*NSEQ*NSEQ];   // 256 MB
__device__ float g_oh[NB*NSEQ*CDIM];

#define EPI_QKV  0
#define EPI_DOTS 1
#define EPI_PV   2
#define EPI_OUT  3

using FragAR = wmma::fragment<wmma::matrix_a, 16, 16, 8, wmma::precision::tf32, wmma::row_major>;
using FragBR = wmma::fragment<wmma::matrix_b, 16, 16, 8, wmma::precision::tf32, wmma::row_major>;
using FragBC = wmma::fragment<wmma::matrix_b, 16, 16, 8, wmma::precision::tf32, wmma::col_major>;
using FragC  = wmma::fragment<wmma::accumulator, 16, 16, 8, float>;

__device__ __forceinline__ float tf32r(float v) { return wmma::__float_to_tf32(v); }

// ---------------------------------------------------------------------------
// 2-term tf32-split wmma GEMM. Tile 128x64, BK=32, double-buffered, 1 sync/tile.
// A pre-split to (hi, lo) tf32 in smem at staging; B pre-converted tf32.
// D = Ah*B + Al*B  (B single tf32; error ~7e-5 RMS per GEMM)
// ---------------------------------------------------------------------------
template<int EPI, int KD, int LDA_, int LDB_, bool TRANSB>
__global__ __launch_bounds__(256, 2)
void tgemm(const float* __restrict__ Ain, const float* __restrict__ Bin,
           float* __restrict__ Cout)
{
    constexpr int BM = 128, BN = 64, BK = 32, KT = KD / BK;
    constexpr int LDAS = 36;
    constexpr int A_STG = BM * LDAS;                       // 4608 floats / stage
    constexpr int B_STG = TRANSB ? (BN * 36) : (BK * 68);

    extern __shared__ float sm[];
    float* AsH = sm;                   // [2][A_STG]
    float* AsL = sm + 2 * A_STG;       // [2][A_STG]
    float* Bs  = sm + 4 * A_STG;       // [2][B_STG]

    const int t   = threadIdx.x;
    const int wid = t >> 5;
    const int wm  = wid & 3, wn = wid >> 2;
    const int m0  = blockIdx.y * BM;
    const int n0  = blockIdx.x * BN;
    const int z   = blockIdx.z;

    const float* Ap;
    const float* Bp;
    if      constexpr (EPI == EPI_QKV)  { Ap = Ain;                     Bp = Bin; }
    else if constexpr (EPI == EPI_DOTS) { Ap = g_q + (size_t)z*NSEQ*HD; Bp = g_k + (size_t)z*NSEQ*HD; }
    else if constexpr (EPI == EPI_PV)   { Ap = g_s + ((size_t)z << 20); Bp = g_v + (size_t)z*NSEQ*HD; }
    else                                { Ap = g_oh;                    Bp = Bin; }

    float4 rA[4], rB[2];

    auto fetchA = [&](int k0) {
        #pragma unroll
        for (int i = 0; i < 4; i++) {
            const int idx = t + i*256;
            const int row = idx >> 3, k4 = (idx & 7) * 4;
            rA[i] = *reinterpret_cast<const float4*>(Ap + (size_t)(m0 + row) * LDA_ + k0 + k4);
        }
    };
    auto fetchB = [&](int k0) {
        #pragma unroll
        for (int i = 0; i < 2; i++) {
            const int idx = t + i*256;
            if constexpr (TRANSB) {
                const int row = idx >> 3, k4 = (idx & 7) * 4;
                rB[i] = *reinterpret_cast<const float4*>(Bp + (size_t)(n0 + row) * LDB_ + k0 + k4);
            } else {
                const int row = idx >> 4, n4 = (idx & 15) * 4;
                rB[i] = *reinterpret_cast<const float4*>(Bp + (size_t)(k0 + row) * LDB_ + n0 + n4);
            }
        }
    };
    auto stage = [&](int st) {
        float* ah = AsH + st * A_STG;
        float* al = AsL + st * A_STG;
        #pragma unroll
        for (int i = 0; i < 4; i++) {
            const int idx = t + i*256;
            const int row = idx >> 3, k4 = (idx & 7) * 4;
            float4 h, l;
            h.x = tf32r(rA[i].x); l.x = tf32r(rA[i].x - h.x);
            h.y = tf32r(rA[i].y); l.y = tf32r(rA[i].y - h.y);
            h.z = tf32r(rA[i].z); l.z = tf32r(rA[i].z - h.z);
            h.w = tf32r(rA[i].w); l.w = tf32r(rA[i].w - h.w);
            *reinterpret_cast<float4*>(ah + row*LDAS + k4) = h;
            *reinterpret_cast<float4*>(al + row*LDAS + k4) = l;
        }
        float* b = Bs + st * B_STG;
        #pragma unroll
        for (int i = 0; i < 2; i++) {
            const int idx = t + i*256;
            float4 v = rB[i];
            v.x = tf32r(v.x); v.y = tf32r(v.y); v.z = tf32r(v.z); v.w = tf32r(v.w);
            if constexpr (TRANSB) {
                const int row = idx >> 3, k4 = (idx & 7) * 4;
                *reinterpret_cast<float4*>(b + row*36 + k4) = v;
            } else {
                const int row = idx >> 4, n4 = (idx & 15) * 4;
                *reinterpret_cast<float4*>(b + row*68 + n4) = v;
            }
        }
    };

    FragC acc[2][2];
    #pragma unroll
    for (int i = 0; i < 2; i++)
        #pragma unroll
        for (int j = 0; j < 2; j++) wmma::fill_fragment(acc[i][j], 0.f);

    fetchA(0); fetchB(0);
    stage(0);
    __syncthreads();

    for (int kt = 0; kt < KT; kt++) {
        const int st = kt & 1;
        if (kt + 1 < KT) { fetchA((kt+1)*BK); fetchB((kt+1)*BK); }

        const float* ah = AsH + st * A_STG;
        const float* al = AsL + st * A_STG;
        const float* b  = Bs  + st * B_STG;
        #pragma unroll
        for (int ks = 0; ks < 4; ks++) {
            FragAR fah[2], fal[2];
            #pragma unroll
            for (int im = 0; im < 2; im++) {
                wmma::load_matrix_sync(fah[im], ah + (wm*32 + im*16)*LDAS + ks*8, LDAS);
                wmma::load_matrix_sync(fal[im], al + (wm*32 + im*16)*LDAS + ks*8, LDAS);
            }
            if constexpr (TRANSB) {
                FragBC fb[2];
                #pragma unroll
                for (int in_ = 0; in_ < 2; in_++)
                    wmma::load_matrix_sync(fb[in_], b + (wn*32 + in_*16)*36 + ks*8, 36);
                #pragma unroll
                for (int im = 0; im < 2; im++)
                    #pragma unroll
                    for (int in_ = 0; in_ < 2; in_++) {
                        wmma::mma_sync(acc[im][in_], fah[im], fb[in_], acc[im][in_]);
                        wmma::mma_sync(acc[im][in_], fal[im], fb[in_], acc[im][in_]);
                    }
            } else {
                FragBR fb[2];
                #pragma unroll
                for (int in_ = 0; in_ < 2; in_++)
                    wmma::load_matrix_sync(fb[in_], b + (ks*8)*68 + wn*32 + in_*16, 68);
                #pragma unroll
                for (int im = 0; im < 2; im++)
                    #pragma unroll
                    for (int in_ = 0; in_ < 2; in_++) {
                        wmma::mma_sync(acc[im][in_], fah[im], fb[in_], acc[im][in_]);
                        wmma::mma_sync(acc[im][in_], fal[im], fb[in_], acc[im][in_]);
                    }
            }
        }

        if (kt + 1 < KT) stage(st ^ 1);
        __syncthreads();
    }

    // direct-to-global epilogue
    float* dst; int ldd;
    if constexpr (EPI == EPI_QKV) {
        const int part = n0 >> 9, h = (n0 & 511) >> 6;
        const int b = m0 >> 10, nr = m0 & 1023;
        float* base = (part == 0) ? g_q : (part == 1) ? g_k : g_v;
        dst = base + (((size_t)(b*NH + h))*NSEQ + nr)*HD;
        ldd = HD;
    } else if constexpr (EPI == EPI_DOTS) {
        dst = g_s + ((size_t)z << 20) + (size_t)m0*NSEQ + n0;
        ldd = NSEQ;
        #pragma unroll
        for (int im = 0; im < 2; im++)
            #pragma unroll
            for (int in_ = 0; in_ < 2; in_++)
                #pragma unroll
                for (int e = 0; e < acc[0][0].num_elements; e++)
                    acc[im][in_].x[e] *= 0.125f;
    } else if constexpr (EPI == EPI_PV) {
        const int b = z >> 3, h = z & 7;
        dst = g_oh + ((size_t)(b*NSEQ + m0))*CDIM + h*HD + n0;
        ldd = CDIM;
    } else {
        dst = Cout + (size_t)m0*CDIM + n0;
        ldd = CDIM;
    }
    #pragma unroll
    for (int im = 0; im < 2; im++)
        #pragma unroll
        for (int in_ = 0; in_ < 2; in_++)
            wmma::store_matrix_sync(dst + (size_t)(wm*32 + im*16)*ldd + wn*32 + in_*16,
                                    acc[im][in_], ldd, wmma::mem_row_major);
}

__global__ void bias_add_k(float* __restrict__ out, const float* __restrict__ bias)
{
    const int i = blockIdx.x * blockDim.x + threadIdx.x;
    out[i] += bias[i & (CDIM-1)];
}

// ---------------------------------------------------------------------------
// softmax + remix + LN (unchanged; in-place on g_s)
// ---------------------------------------------------------------------------
__global__ __launch_bounds__(256)
void softmax_remix_ln(const float* __restrict__ W,
                      const float* __restrict__ gamma,
                      const float* __restrict__ beta)
{
    __shared__ float s[NH][NSEQ];
    __shared__ float w_s[64], g_s_[8], b_s_[8];

    const int t = threadIdx.x;
    const int bi = blockIdx.x;
    const int b = bi >> 10, i = bi & 1023;

    if (t < 64) w_s[t] = W[t];
    if (t >= 64 && t < 72) { g_s_[t-64] = gamma[t-64]; b_s_[t-64] = beta[t-64]; }

    const int wid = t >> 5, lid = t & 31;
    {
        const float* row = g_s + (((size_t)(b*NH + wid))*NSEQ + i)*NSEQ;
        float v[32], m = -1e30f;
        #pragma unroll
        for (int u = 0; u < 32; u++) { v[u] = row[lid + 32*u]; m = fmaxf(m, v[u]); }
        #pragma unroll
        for (int o = 16; o > 0; o >>= 1) m = fmaxf(m, __shfl_xor_sync(0xffffffffu, m, o));
        float sum = 0.f;
        #pragma unroll
        for (int u = 0; u < 32; u++) { v[u] = __expf(v[u] - m); sum += v[u]; }
        #pragma unroll
        for (int o = 16; o > 0; o >>= 1) sum += __shfl_xor_sync(0xffffffffu, sum, o);
        const float inv = 1.f / sum;
        #pragma unroll
        for (int u = 0; u < 32; u++) s[wid][lid + 32*u] = v[u] * inv;
    }
    __syncthreads();

    #pragma unroll
    for (int u = 0; u < 4; u++) {
        const int j = t + 256*u;
        float a[8], mres[8];
        #pragma unroll
        for (int h = 0; h < 8; h++) a[h] = s[h][j];
        float mean = 0.f;
        #pragma unroll
        for (int g = 0; g < 8; g++) {
            float acc = 0.f;
            #pragma unroll
            for (int h = 0; h < 8; h++) acc += a[h] * w_s[h*8 + g];
            mres[g] = acc; mean += acc;
        }
        mean *= 0.125f;
        float var = 0.f;
        #pragma unroll
        for (int g = 0; g < 8; g++) { float d = mres[g] - mean; var += d*d; }
        var *= 0.125f;
        const float rstd = rsqrtf(var + 1e-5f);
        #pragma unroll
        for (int g = 0; g < 8; g++) {
            const float o = (mres[g] - mean) * rstd * g_s_[g] + b_s_[g];
            g_s[(((size_t)(b*NH + g))*NSEQ + i)*NSEQ + j] = o;
        }
    }
}

// ---------------------------------------------------------------------------
extern "C" void kernel_launch(void* const* d_in, const int* in_sizes, int n_in,
                              void* d_out, int out_size)
{
    const float* x      = (const float*)d_in[0];
    const float* w_qkv  = (const float*)d_in[1];
    const float* reattn = (const float*)d_in[2];
    const float* gamma  = (const float*)d_in[3];
    const float* beta   = (const float*)d_in[4];
    const float* w_out  = (const float*)d_in[5];
    const float* b_out  = (const float*)d_in[6];
    float* out = (float*)d_out;

    constexpr int A_BYTES = 4*128*36*4;                // 73728 (hi+lo, 2 stages)
    constexpr int SM_ROW  = A_BYTES + 2*32*68*4;       // 91136
    constexpr int SM_COL  = A_BYTES + 2*64*36*4;       // 92160

    cudaFuncSetAttribute(tgemm<EPI_QKV, 512, 512, 1536, false>, cudaFuncAttributeMaxDynamicSharedMemorySize, SM_ROW);
    cudaFuncSetAttribute(tgemm<EPI_DOTS, 64, 64, 64, true>,     cudaFuncAttributeMaxDynamicSharedMemorySize, SM_COL);
    cudaFuncSetAttribute(tgemm<EPI_PV, 1024, 1024, 64, false>,  cudaFuncAttributeMaxDynamicSharedMemorySize, SM_ROW);
    cudaFuncSetAttribute(tgemm<EPI_OUT, 512, 512, 512, false>,  cudaFuncAttributeMaxDynamicSharedMemorySize, SM_ROW);

    // 1) qkv = x @ w_qkv -> scatter g_q/g_k/g_v
    tgemm<EPI_QKV, 512, 512, 1536, false>
        <<<dim3(24, 64, 1), 256, SM_ROW>>>(x, w_qkv, nullptr);
    // 2) dots = q @ k^T * scale
    tgemm<EPI_DOTS, 64, 64, 64, true>
        <<<dim3(16, 8, 64), 256, SM_COL>>>(nullptr, nullptr, nullptr);
    // 3) softmax + remix + LN (in place on g_s)
    softmax_remix_ln<<<NB*NSEQ, 256>>>(reattn, gamma, beta);
    // 4) out_h = attn @ v
    tgemm<EPI_PV, 1024, 1024, 64, false>
        <<<dim3(1, 8, 64), 256, SM_ROW>>>(nullptr, nullptr, nullptr);
    // 5) out = g_oh @ w_out ; then + b_out
    tgemm<EPI_OUT, 512, 512, 512, false>
        <<<dim3(8, 64, 1), 256, SM_ROW>>>(nullptr, w_out, out);
    bias_add_k<<<(8192*512)/256, 256>>>(out, b_out);
}

// round 11
// speedup vs baseline: 2.4706x; 1.8111x over previous
#include <cuda_runtime.h>
#include <cuda_bf16.h>
#include <mma.h>
#include <cstdint>

using namespace nvcuda;

#define NB 8
#define NSEQ 1024
#define NH 8
#define HD 64
#define CDIM 512

__device__ float g_q[NB*NH*NSEQ*HD];
__device__ float g_k[NB*NH*NSEQ*HD];
__device__ float g_v[NB*NH*NSEQ*HD];
__device__ float g_s[(size_t)NB*NH*NSEQ*NSEQ];   // 256 MB
__device__ float g_oh[NB*NSEQ*CDIM];

#define EPI_QKV  0
#define EPI_DOTS 1
#define EPI_PV   2
#define EPI_OUT  3

using FragA  = wmma::fragment<wmma::matrix_a, 16, 16, 16, __nv_bfloat16, wmma::row_major>;
using FragBR = wmma::fragment<wmma::matrix_b, 16, 16, 16, __nv_bfloat16, wmma::row_major>;
using FragBC = wmma::fragment<wmma::matrix_b, 16, 16, 16, __nv_bfloat16, wmma::col_major>;
using FragC  = wmma::fragment<wmma::accumulator, 16, 16, 16, float>;

__device__ __forceinline__ void split4(const float4 v, uint2& hi, uint2& lo) {
    __nv_bfloat16 hx = __float2bfloat16(v.x), hy = __float2bfloat16(v.y);
    __nv_bfloat16 hz = __float2bfloat16(v.z), hw = __float2bfloat16(v.w);
    __nv_bfloat16 lx = __float2bfloat16(v.x - __bfloat162float(hx));
    __nv_bfloat16 ly = __float2bfloat16(v.y - __bfloat162float(hy));
    __nv_bfloat16 lz = __float2bfloat16(v.z - __bfloat162float(hz));
    __nv_bfloat16 lw = __float2bfloat16(v.w - __bfloat162float(hw));
    __nv_bfloat162 h0{hx, hy}, h1{hz, hw}, l0{lx, ly}, l1{lz, lw};
    hi.x = *reinterpret_cast<unsigned int*>(&h0); hi.y = *reinterpret_cast<unsigned int*>(&h1);
    lo.x = *reinterpret_cast<unsigned int*>(&l0); lo.y = *reinterpret_cast<unsigned int*>(&l1);
}

// ---------------------------------------------------------------------------
// 3-term bf16-split wmma GEMM (D += Ah*Bh + Al*Bh + Ah*Bl; err ~1e-5).
// BM=128, BK=32 (2 wmma k16-steps), BN = 64 or 128; 8 warps (4m x 2n),
// double-buffered smem, 1 sync/tile, direct-to-global epilogue.
// ---------------------------------------------------------------------------
template<int EPI, int KD, int LDA_, int LDB_, bool TRANSB, int BN>
__global__ __launch_bounds__(256, 2)
void tgemm(const float* __restrict__ Ain, const float* __restrict__ Bin,
           float* __restrict__ Cout)
{
    constexpr int BM = 128, BK = 32, KT = KD / BK;
    constexpr int FN = BN / 32;              // n-frags per warp (2 or 4)
    constexpr int WN = BN / 2;               // warp n-span
    constexpr int LDAS = 40;                 // halfs per A row (32 + 8 pad)
    constexpr int A_STG = BM * LDAS;         // halfs per A stage plane
    constexpr int LDBS = TRANSB ? 40 : (BN + 8);
    constexpr int B_STG = TRANSB ? (BN * 40) : (BK * (BN + 8));
    constexpr int NB4 = BN / 32;             // B float4 fetches per thread

    extern __shared__ __align__(128) __nv_bfloat16 sm[];
    __nv_bfloat16* AsH = sm;                       // [2][A_STG]
    __nv_bfloat16* AsL = sm + 2*A_STG;
    __nv_bfloat16* BsH = sm + 4*A_STG;             // [2][B_STG]
    __nv_bfloat16* BsL = sm + 4*A_STG + 2*B_STG;

    const int t   = threadIdx.x;
    const int wid = t >> 5;
    const int wm  = wid & 3, wn = wid >> 2;
    const int m0  = blockIdx.y * BM;
    const int n0  = blockIdx.x * BN;
    const int z   = blockIdx.z;

    const float* Ap;
    const float* Bp;
    if      constexpr (EPI == EPI_QKV)  { Ap = Ain;                     Bp = Bin; }
    else if constexpr (EPI == EPI_DOTS) { Ap = g_q + (size_t)z*NSEQ*HD; Bp = g_k + (size_t)z*NSEQ*HD; }
    else if constexpr (EPI == EPI_PV)   { Ap = g_s + ((size_t)z << 20); Bp = g_v + (size_t)z*NSEQ*HD; }
    else                                { Ap = g_oh;                    Bp = Bin; }

    float4 rA[4], rB[NB4];

    auto fetchA = [&](int k0) {
        #pragma unroll
        for (int i = 0; i < 4; i++) {
            const int idx = t + i*256;
            const int row = idx >> 3, k4 = (idx & 7) * 4;
            rA[i] = *reinterpret_cast<const float4*>(Ap + (size_t)(m0 + row) * LDA_ + k0 + k4);
        }
    };
    auto fetchB = [&](int k0) {
        #pragma unroll
        for (int i = 0; i < NB4; i++) {
            const int idx = t + i*256;
            if constexpr (TRANSB) {
                const int row = idx >> 3, k4 = (idx & 7) * 4;
                rB[i] = *reinterpret_cast<const float4*>(Bp + (size_t)(n0 + row) * LDB_ + k0 + k4);
            } else {
                constexpr int R4 = BN / 4;   // float4 per k-row
                const int row = idx / R4, n4 = (idx % R4) * 4;
                rB[i] = *reinterpret_cast<const float4*>(Bp + (size_t)(k0 + row) * LDB_ + n0 + n4);
            }
        }
    };
    auto stage = [&](int st) {
        __nv_bfloat16* ah = AsH + st*A_STG;
        __nv_bfloat16* al = AsL + st*A_STG;
        #pragma unroll
        for (int i = 0; i < 4; i++) {
            const int idx = t + i*256;
            const int row = idx >> 3, k4 = (idx & 7) * 4;
            uint2 hi, lo; split4(rA[i], hi, lo);
            *reinterpret_cast<uint2*>(ah + row*LDAS + k4) = hi;
            *reinterpret_cast<uint2*>(al + row*LDAS + k4) = lo;
        }
        __nv_bfloat16* bh = BsH + st*B_STG;
        __nv_bfloat16* bl = BsL + st*B_STG;
        #pragma unroll
        for (int i = 0; i < NB4; i++) {
            const int idx = t + i*256;
            uint2 hi, lo; split4(rB[i], hi, lo);
            if constexpr (TRANSB) {
                const int row = idx >> 3, k4 = (idx & 7) * 4;
                *reinterpret_cast<uint2*>(bh + row*LDBS + k4) = hi;
                *reinterpret_cast<uint2*>(bl + row*LDBS + k4) = lo;
            } else {
                constexpr int R4 = BN / 4;
                const int row = idx / R4, n4 = (idx % R4) * 4;
                *reinterpret_cast<uint2*>(bh + row*LDBS + n4) = hi;
                *reinterpret_cast<uint2*>(bl + row*LDBS + n4) = lo;
            }
        }
    };

    FragC acc[2][FN];
    #pragma unroll
    for (int i = 0; i < 2; i++)
        #pragma unroll
        for (int j = 0; j < FN; j++) wmma::fill_fragment(acc[i][j], 0.f);

    fetchA(0); fetchB(0);
    stage(0);
    __syncthreads();

    for (int kt = 0; kt < KT; kt++) {
        const int st = kt & 1;
        if (kt + 1 < KT) { fetchA((kt+1)*BK); fetchB((kt+1)*BK); }

        const __nv_bfloat16* ah = AsH + st*A_STG;
        const __nv_bfloat16* al = AsL + st*A_STG;
        const __nv_bfloat16* bh = BsH + st*B_STG;
        const __nv_bfloat16* bl = BsL + st*B_STG;

        #pragma unroll
        for (int ks = 0; ks < 2; ks++) {
            FragA fah[2], fal[2];
            #pragma unroll
            for (int im = 0; im < 2; im++) {
                const int ro = (wm*32 + im*16)*LDAS + ks*16;
                wmma::load_matrix_sync(fah[im], ah + ro, LDAS);
                wmma::load_matrix_sync(fal[im], al + ro, LDAS);
            }
            if constexpr (TRANSB) {
                FragBC fbh[FN], fbl[FN];
                #pragma unroll
                for (int in_ = 0; in_ < FN; in_++) {
                    const int bo = (wn*WN + in_*16)*LDBS + ks*16;
                    wmma::load_matrix_sync(fbh[in_], bh + bo, LDBS);
                    wmma::load_matrix_sync(fbl[in_], bl + bo, LDBS);
                }
                #pragma unroll
                for (int im = 0; im < 2; im++)
                    #pragma unroll
                    for (int in_ = 0; in_ < FN; in_++) {
                        wmma::mma_sync(acc[im][in_], fah[im], fbh[in_], acc[im][in_]);
                        wmma::mma_sync(acc[im][in_], fal[im], fbh[in_], acc[im][in_]);
                        wmma::mma_sync(acc[im][in_], fah[im], fbl[in_], acc[im][in_]);
                    }
            } else {
                FragBR fbh[FN], fbl[FN];
                #pragma unroll
                for (int in_ = 0; in_ < FN; in_++) {
                    const int bo = (ks*16)*LDBS + wn*WN + in_*16;
                    wmma::load_matrix_sync(fbh[in_], bh + bo, LDBS);
                    wmma::load_matrix_sync(fbl[in_], bl + bo, LDBS);
                }
                #pragma unroll
                for (int im = 0; im < 2; im++)
                    #pragma unroll
                    for (int in_ = 0; in_ < FN; in_++) {
                        wmma::mma_sync(acc[im][in_], fah[im], fbh[in_], acc[im][in_]);
                        wmma::mma_sync(acc[im][in_], fal[im], fbh[in_], acc[im][in_]);
                        wmma::mma_sync(acc[im][in_], fah[im], fbl[in_], acc[im][in_]);
                    }
            }
        }

        if (kt + 1 < KT) stage(st ^ 1);
        __syncthreads();
    }

    // direct-to-global epilogue, per 16x16 fragment
    #pragma unroll
    for (int im = 0; im < 2; im++) {
        const int row0 = m0 + wm*32 + im*16;
        #pragma unroll
        for (int in_ = 0; in_ < FN; in_++) {
            const int c0 = n0 + wn*WN + in_*16;
            if constexpr (EPI == EPI_QKV) {
                const int part = c0 >> 9, h = (c0 & 511) >> 6, d = c0 & 63;
                const int b = row0 >> 10, nr = row0 & 1023;
                float* base = (part == 0) ? g_q : (part == 1) ? g_k : g_v;
                wmma::store_matrix_sync(base + (((size_t)(b*NH + h))*NSEQ + nr)*HD + d,
                                        acc[im][in_], HD, wmma::mem_row_major);
            } else if constexpr (EPI == EPI_DOTS) {
                #pragma unroll
                for (int e = 0; e < acc[0][0].num_elements; e++) acc[im][in_].x[e] *= 0.125f;
                wmma::store_matrix_sync(g_s + ((size_t)z << 20) + (size_t)row0*NSEQ + c0,
                                        acc[im][in_], NSEQ, wmma::mem_row_major);
            } else if constexpr (EPI == EPI_PV) {
                const int b = z >> 3, h = z & 7;
                wmma::store_matrix_sync(g_oh + ((size_t)(b*NSEQ + row0))*CDIM + h*HD + c0,
                                        acc[im][in_], CDIM, wmma::mem_row_major);
            } else {
                wmma::store_matrix_sync(Cout + (size_t)row0*CDIM + c0,
                                        acc[im][in_], CDIM, wmma::mem_row_major);
            }
        }
    }
}

__global__ void bias_add_k(float* __restrict__ out, const float* __restrict__ bias)
{
    const int i = blockIdx.x * blockDim.x + threadIdx.x;
    out[i] += bias[i & (CDIM-1)];
}

// ---------------------------------------------------------------------------
// softmax + remix + LN (unchanged; in-place on g_s)
// ---------------------------------------------------------------------------
__global__ __launch_bounds__(256)
void softmax_remix_ln(const float* __restrict__ W,
                      const float* __restrict__ gamma,
                      const float* __restrict__ beta)
{
    __shared__ float s[NH][NSEQ];
    __shared__ float w_s[64], g_s_[8], b_s_[8];

    const int t = threadIdx.x;
    const int bi = blockIdx.x;
    const int b = bi >> 10, i = bi & 1023;

    if (t < 64) w_s[t] = W[t];
    if (t >= 64 && t < 72) { g_s_[t-64] = gamma[t-64]; b_s_[t-64] = beta[t-64]; }

    const int wid = t >> 5, lid = t & 31;
    {
        const float* row = g_s + (((size_t)(b*NH + wid))*NSEQ + i)*NSEQ;
        float v[32], m = -1e30f;
        #pragma unroll
        for (int u = 0; u < 32; u++) { v[u] = row[lid + 32*u]; m = fmaxf(m, v[u]); }
        #pragma unroll
        for (int o = 16; o > 0; o >>= 1) m = fmaxf(m, __shfl_xor_sync(0xffffffffu, m, o));
        float sum = 0.f;
        #pragma unroll
        for (int u = 0; u < 32; u++) { v[u] = __expf(v[u] - m); sum += v[u]; }
        #pragma unroll
        for (int o = 16; o > 0; o >>= 1) sum += __shfl_xor_sync(0xffffffffu, sum, o);
        const float inv = 1.f / sum;
        #pragma unroll
        for (int u = 0; u < 32; u++) s[wid][lid + 32*u] = v[u] * inv;
    }
    __syncthreads();

    #pragma unroll
    for (int u = 0; u < 4; u++) {
        const int j = t + 256*u;
        float a[8], mres[8];
        #pragma unroll
        for (int h = 0; h < 8; h++) a[h] = s[h][j];
        float mean = 0.f;
        #pragma unroll
        for (int g = 0; g < 8; g++) {
            float acc = 0.f;
            #pragma unroll
            for (int h = 0; h < 8; h++) acc += a[h] * w_s[h*8 + g];
            mres[g] = acc; mean += acc;
        }
        mean *= 0.125f;
        float var = 0.f;
        #pragma unroll
        for (int g = 0; g < 8; g++) { float d = mres[g] - mean; var += d*d; }
        var *= 0.125f;
        const float rstd = rsqrtf(var + 1e-5f);
        #pragma unroll
        for (int g = 0; g < 8; g++) {
            const float o = (mres[g] - mean) * rstd * g_s_[g] + b_s_[g];
            g_s[(((size_t)(b*NH + g))*NSEQ + i)*NSEQ + j] = o;
        }
    }
}

// ---------------------------------------------------------------------------
extern "C" void kernel_launch(void* const* d_in, const int* in_sizes, int n_in,
                              void* d_out, int out_size)
{
    const float* x      = (const float*)d_in[0];
    const float* w_qkv  = (const float*)d_in[1];
    const float* reattn = (const float*)d_in[2];
    const float* gamma  = (const float*)d_in[3];
    const float* beta   = (const float*)d_in[4];
    const float* w_out  = (const float*)d_in[5];
    const float* b_out  = (const float*)d_in[6];
    float* out = (float*)d_out;

    // smem bytes = 2 * (4*A_STG + 4*B_STG) halfs
    constexpr int SM_QKV  = 2*(4*128*40 + 4*32*136);   // 75776
    constexpr int SM_DOTS = 2*(4*128*40 + 4*128*40);   // 81920
    constexpr int SM_PV   = 2*(4*128*40 + 4*32*72);    // 59392
    constexpr int SM_OUT  = SM_QKV;

    cudaFuncSetAttribute(tgemm<EPI_QKV, 512, 512, 1536, false, 128>, cudaFuncAttributeMaxDynamicSharedMemorySize, SM_QKV);
    cudaFuncSetAttribute(tgemm<EPI_DOTS, 64, 64, 64, true, 128>,     cudaFuncAttributeMaxDynamicSharedMemorySize, SM_DOTS);
    cudaFuncSetAttribute(tgemm<EPI_PV, 1024, 1024, 64, false, 64>,   cudaFuncAttributeMaxDynamicSharedMemorySize, SM_PV);
    cudaFuncSetAttribute(tgemm<EPI_OUT, 512, 512, 512, false, 128>,  cudaFuncAttributeMaxDynamicSharedMemorySize, SM_OUT);

    // 1) qkv = x @ w_qkv -> scatter g_q/g_k/g_v
    tgemm<EPI_QKV, 512, 512, 1536, false, 128>
        <<<dim3(12, 64, 1), 256, SM_QKV>>>(x, w_qkv, nullptr);
    // 2) dots = q @ k^T * scale
    tgemm<EPI_DOTS, 64, 64, 64, true, 128>
        <<<dim3(8, 8, 64), 256, SM_DOTS>>>(nullptr, nullptr, nullptr);
    // 3) softmax + remix + LN (in place on g_s)
    softmax_remix_ln<<<NB*NSEQ, 256>>>(reattn, gamma, beta);
    // 4) out_h = attn @ v
    tgemm<EPI_PV, 1024, 1024, 64, false, 64>
        <<<dim3(1, 8, 64), 256, SM_PV>>>(nullptr, nullptr, nullptr);
    // 5) out = g_oh @ w_out ; then + b_out
    tgemm<EPI_OUT, 512, 512, 512, false, 128>
        <<<dim3(4, 64, 1), 256, SM_OUT>>>(nullptr, w_out, out);
    bias_add_k<<<(8192*512)/256, 256>>>(out, b_out);
}